// round 1
// baseline (speedup 1.0000x reference)
#include <cuda_runtime.h>

#define BATCH   2
#define NHEADS  12
#define SEQLEN  2048
#define DMODEL  768
#define DK      64

// ---------------- scratch (no allocations allowed) ----------------
__device__ float g_q[(size_t)BATCH * NHEADS * SEQLEN * DK];   // 12 MB
__device__ float g_k[(size_t)BATCH * NHEADS * SEQLEN * DK];   // 12 MB
__device__ float g_v[(size_t)BATCH * NHEADS * SEQLEN * DK];   // 12 MB
__device__ float g_o[(size_t)BATCH * SEQLEN * DMODEL];        // 12 MB

// =====================================================================
// Tiled fp32 GEMM: C = A(M,K) @ W(K,N) + bias(N)
// BM=BN=128, BK=16, 256 threads, 8x8 register micro-tile per thread.
// MODE 0: write C row-major to `out`. A==nullptr means A=g_o.
// MODE 1: scatter columns into g_q/g_k/g_v head-major layout (QKV).
// All dims are exact multiples of tile sizes for this problem.
// =====================================================================
template <int MODE>
__global__ __launch_bounds__(256, 2)
void gemm128(const float* __restrict__ A, const float* __restrict__ W,
             const float* __restrict__ bias, float* __restrict__ out,
             int M, int N, int K)
{
    if (MODE == 0 && A == nullptr) A = g_o;

    __shared__ float As[16][132];   // k-major (transposed) with pad
    __shared__ float Bs[16][128];

    const int tid = threadIdx.x;
    const int bm  = blockIdx.y * 128;
    const int bn  = blockIdx.x * 128;
    const int tx  = tid & 15;
    const int ty  = tid >> 4;

    float acc[8][8];
#pragma unroll
    for (int i = 0; i < 8; ++i)
#pragma unroll
        for (int j = 0; j < 8; ++j) acc[i][j] = 0.f;

    for (int k0 = 0; k0 < K; k0 += 16) {
        // A tile (128 x 16) -> As[k][m]
        {
            const int row  = tid >> 2;           // 0..63
            const int kseg = (tid & 3) * 4;      // 0,4,8,12
#pragma unroll
            for (int it = 0; it < 2; ++it) {
                const int r = row + it * 64;
                const float4 v = *(const float4*)&A[(size_t)(bm + r) * K + k0 + kseg];
                As[kseg + 0][r] = v.x;
                As[kseg + 1][r] = v.y;
                As[kseg + 2][r] = v.z;
                As[kseg + 3][r] = v.w;
            }
        }
        // B tile (16 x 128) -> Bs[k][n]
        {
            const int r  = tid >> 5;             // 0..7
            const int c4 = (tid & 31) * 4;       // 0..124
#pragma unroll
            for (int it = 0; it < 2; ++it) {
                const int rr = r + it * 8;
                *(float4*)&Bs[rr][c4] =
                    *(const float4*)&W[(size_t)(k0 + rr) * N + bn + c4];
            }
        }
        __syncthreads();

#pragma unroll
        for (int k = 0; k < 16; ++k) {
            float a[8], b[8];
            *(float4*)&a[0] = *(const float4*)&As[k][ty * 8];
            *(float4*)&a[4] = *(const float4*)&As[k][ty * 8 + 4];
            *(float4*)&b[0] = *(const float4*)&Bs[k][tx * 8];
            *(float4*)&b[4] = *(const float4*)&Bs[k][tx * 8 + 4];
#pragma unroll
            for (int i = 0; i < 8; ++i)
#pragma unroll
                for (int j = 0; j < 8; ++j)
                    acc[i][j] = fmaf(a[i], b[j], acc[i][j]);
        }
        __syncthreads();
    }

    // epilogue
#pragma unroll
    for (int i = 0; i < 8; ++i) {
        const int m  = bm + ty * 8 + i;
        const int b_ = m / SEQLEN;
        const int l  = m % SEQLEN;
#pragma unroll
        for (int j = 0; j < 8; ++j) {
            const int n = bn + tx * 8 + j;
            const float vv = acc[i][j] + bias[n];
            if (MODE == 0) {
                out[(size_t)m * N + n] = vv;
            } else {
                const int part = n / DMODEL;        // 0=q 1=k 2=v
                const int w    = n % DMODEL;
                const int h    = w / DK;
                const int d    = w % DK;
                float* dst = (part == 0) ? g_q : (part == 1) ? g_k : g_v;
                dst[(((size_t)b_ * NHEADS + h) * SEQLEN + l) * DK + d] = vv;
            }
        }
    }
}

// =====================================================================
// Flash attention: BM=BN=64, dk=64, 256 threads, online softmax.
// Thread (ty,tx): ty=tid/16 owns rows ty*4..+3, tx owns cols tx*4..+3.
// Row groups of 16 threads are contiguous lanes -> width-16 shuffles.
// Smem: Qs,Ks [d][r] (transposed, stride 68), Vs,Ps row-major stride 68.
// =====================================================================
#define ATTN_STRIDE 68
#define ATTN_SMEM_FLOATS (4 * 64 * ATTN_STRIDE + 64)

__global__ void attn_kernel(const int* __restrict__ amask)
{
    extern __shared__ float sm[];
    float* Qs   = sm;
    float* Ks   = Qs + 64 * ATTN_STRIDE;
    float* Vs   = Ks + 64 * ATTN_STRIDE;
    float* Ps   = Vs + 64 * ATTN_STRIDE;
    float* madd = Ps + 64 * ATTN_STRIDE;

    const int tid = threadIdx.x;
    const int bh  = blockIdx.y;              // b*NHEADS + h
    const int b   = bh / NHEADS;
    const int h   = bh % NHEADS;
    const int qb  = blockIdx.x * 64;

    const float* Q  = g_q + (size_t)bh * SEQLEN * DK;
    const float* Kp = g_k + (size_t)bh * SEQLEN * DK;
    const float* Vp = g_v + (size_t)bh * SEQLEN * DK;

    const int tx = tid & 15, ty = tid >> 4;
    const int r0 = ty * 4, c0 = tx * 4;

    // load Q block transposed: Qs[d][r]
    {
        const int row  = tid >> 2;            // 0..63
        const int dseg = (tid & 3) * 16;
#pragma unroll
        for (int s = 0; s < 4; ++s) {
            const float4 v = *(const float4*)&Q[(size_t)(qb + row) * DK + dseg + s * 4];
            Qs[(dseg + s * 4 + 0) * ATTN_STRIDE + row] = v.x;
            Qs[(dseg + s * 4 + 1) * ATTN_STRIDE + row] = v.y;
            Qs[(dseg + s * 4 + 2) * ATTN_STRIDE + row] = v.z;
            Qs[(dseg + s * 4 + 3) * ATTN_STRIDE + row] = v.w;
        }
    }

    float m_i[4], l_i[4], acc[4][4];
#pragma unroll
    for (int i = 0; i < 4; ++i) {
        m_i[i] = -1e30f; l_i[i] = 0.f;
#pragma unroll
        for (int j = 0; j < 4; ++j) acc[i][j] = 0.f;
    }

    for (int kb = 0; kb < SEQLEN; kb += 64) {
        __syncthreads();   // protect Vs/Ps reads of previous iter (and Q store, iter 0)
        // load K transposed, V natural, mask adds
        {
            const int row  = tid >> 2;
            const int dseg = (tid & 3) * 16;
#pragma unroll
            for (int s = 0; s < 4; ++s) {
                const float4 kv = *(const float4*)&Kp[(size_t)(kb + row) * DK + dseg + s * 4];
                Ks[(dseg + s * 4 + 0) * ATTN_STRIDE + row] = kv.x;
                Ks[(dseg + s * 4 + 1) * ATTN_STRIDE + row] = kv.y;
                Ks[(dseg + s * 4 + 2) * ATTN_STRIDE + row] = kv.z;
                Ks[(dseg + s * 4 + 3) * ATTN_STRIDE + row] = kv.w;
                const float4 vv = *(const float4*)&Vp[(size_t)(kb + row) * DK + dseg + s * 4];
                *(float4*)&Vs[row * ATTN_STRIDE + dseg + s * 4] = vv;
            }
        }
        if (tid < 64) madd[tid] = amask[(size_t)b * SEQLEN + kb + tid] ? 0.f : -1e30f;
        __syncthreads();

        // S = Q @ K^T (64x64 tile, 4x4 per thread)
        float s[4][4];
#pragma unroll
        for (int i = 0; i < 4; ++i)
#pragma unroll
            for (int j = 0; j < 4; ++j) s[i][j] = 0.f;

#pragma unroll 8
        for (int d = 0; d < 64; ++d) {
            const float4 qf = *(const float4*)&Qs[d * ATTN_STRIDE + r0];
            const float4 kf = *(const float4*)&Ks[d * ATTN_STRIDE + c0];
            const float qa[4] = {qf.x, qf.y, qf.z, qf.w};
            const float ka[4] = {kf.x, kf.y, kf.z, kf.w};
#pragma unroll
            for (int i = 0; i < 4; ++i)
#pragma unroll
                for (int j = 0; j < 4; ++j)
                    s[i][j] = fmaf(qa[i], ka[j], s[i][j]);
        }

        const float mb0 = madd[c0 + 0], mb1 = madd[c0 + 1];
        const float mb2 = madd[c0 + 2], mb3 = madd[c0 + 3];
#pragma unroll
        for (int i = 0; i < 4; ++i) {
            s[i][0] = s[i][0] * 0.125f + mb0;
            s[i][1] = s[i][1] * 0.125f + mb1;
            s[i][2] = s[i][2] * 0.125f + mb2;
            s[i][3] = s[i][3] * 0.125f + mb3;
        }

        // online softmax update
        float p[4][4];
#pragma unroll
        for (int i = 0; i < 4; ++i) {
            float mn = fmaxf(fmaxf(s[i][0], s[i][1]), fmaxf(s[i][2], s[i][3]));
#pragma unroll
            for (int off = 8; off > 0; off >>= 1)
                mn = fmaxf(mn, __shfl_xor_sync(0xffffffffu, mn, off, 16));
            mn = fmaxf(mn, m_i[i]);
            const float alpha = __expf(m_i[i] - mn);
            float rs = 0.f;
#pragma unroll
            for (int j = 0; j < 4; ++j) {
                p[i][j] = __expf(s[i][j] - mn);
                rs += p[i][j];
            }
#pragma unroll
            for (int off = 8; off > 0; off >>= 1)
                rs += __shfl_xor_sync(0xffffffffu, rs, off, 16);
            l_i[i] = l_i[i] * alpha + rs;
            m_i[i] = mn;
#pragma unroll
            for (int j = 0; j < 4; ++j) acc[i][j] *= alpha;
        }

        // stage P
#pragma unroll
        for (int i = 0; i < 4; ++i)
            *(float4*)&Ps[(r0 + i) * ATTN_STRIDE + c0] =
                make_float4(p[i][0], p[i][1], p[i][2], p[i][3]);
        __syncthreads();

        // acc += P @ V  (thread owns O rows r0.., dk cols c0..)
#pragma unroll 4
        for (int k = 0; k < 64; k += 4) {
            float pr[4][4];
#pragma unroll
            for (int i = 0; i < 4; ++i)
                *(float4*)&pr[i][0] = *(const float4*)&Ps[(r0 + i) * ATTN_STRIDE + k];
#pragma unroll
            for (int kk = 0; kk < 4; ++kk) {
                const float4 vf = *(const float4*)&Vs[(k + kk) * ATTN_STRIDE + c0];
#pragma unroll
                for (int i = 0; i < 4; ++i) {
                    acc[i][0] = fmaf(pr[i][kk], vf.x, acc[i][0]);
                    acc[i][1] = fmaf(pr[i][kk], vf.y, acc[i][1]);
                    acc[i][2] = fmaf(pr[i][kk], vf.z, acc[i][2]);
                    acc[i][3] = fmaf(pr[i][kk], vf.w, acc[i][3]);
                }
            }
        }
    }

    // write O in (B, L, D) layout: column block = h*64 + c0
#pragma unroll
    for (int i = 0; i < 4; ++i) {
        const float inv = 1.f / l_i[i];
        float* dst = &g_o[((size_t)b * SEQLEN + qb + r0 + i) * DMODEL + h * DK + c0];
        dst[0] = acc[i][0] * inv;
        dst[1] = acc[i][1] * inv;
        dst[2] = acc[i][2] * inv;
        dst[3] = acc[i][3] * inv;
    }
}

// =====================================================================
extern "C" void kernel_launch(void* const* d_in, const int* in_sizes, int n_in,
                              void* d_out, int out_size)
{
    const float* x      = (const float*)d_in[0];
    const int*   amask  = (const int*)  d_in[1];
    const float* w_qkv  = (const float*)d_in[2];
    const float* b_qkv  = (const float*)d_in[3];
    const float* w_out  = (const float*)d_in[4];
    const float* b_out  = (const float*)d_in[5];
    float*       out    = (float*)d_out;

    const int M = BATCH * SEQLEN;   // 4096

    // 1) fused QKV projection -> g_q/g_k/g_v (head-major)
    dim3 g1((3 * DMODEL) / 128, M / 128);
    gemm128<1><<<g1, 256>>>(x, w_qkv, b_qkv, nullptr, M, 3 * DMODEL, DMODEL);

    // 2) flash attention -> g_o (B,L,D)
    const int smem_bytes = ATTN_SMEM_FLOATS * (int)sizeof(float);
    cudaFuncSetAttribute(attn_kernel, cudaFuncAttributeMaxDynamicSharedMemorySize,
                         smem_bytes);
    dim3 g2(SEQLEN / 64, BATCH * NHEADS);
    attn_kernel<<<g2, 256, smem_bytes>>>(amask);

    // 3) output projection -> d_out
    dim3 g3(DMODEL / 128, M / 128);
    gemm128<0><<<g3, 256>>>(nullptr, w_out, b_out, out, M, DMODEL, DMODEL);
}